// round 16
// baseline (speedup 1.0000x reference)
#include <cuda_runtime.h>
#include <cuda_fp16.h>
#include <math.h>
#include <stdint.h>

#define TT   8192
#define EE   1024
#define HH   16
#define DD   64
#define NSEG 8
#define LL   1024

// Scratch (device globals — no allocation allowed in kernel_launch)
__device__ __half g_hh [TT * EE];       // hs in half
__device__ __half g_wh [4 * EE * EE];   // 4 weights in half
__device__ __half g_qh [TT * EE];       // Q projection (half)
__device__ __half g_kh [TT * EE];       // K projection (half)
__device__ __half g_vth[EE * TT];       // V projection, transposed [e][token]
__device__ __half g_oh [TT * EE];       // attention output (half)
__device__ __half g_mkh[TT * LL];       // compacted block-diagonal mask (half)

// ---------------------------------------------------------------------------
// helpers
// ---------------------------------------------------------------------------
__device__ __forceinline__ void ldsm4(uint32_t* r, uint32_t addr) {
    asm volatile("ldmatrix.sync.aligned.m8n8.x4.shared.b16 {%0,%1,%2,%3}, [%4];"
                 : "=r"(r[0]), "=r"(r[1]), "=r"(r[2]), "=r"(r[3]) : "r"(addr));
}
__device__ __forceinline__ void mma16(float* c, const uint32_t* a, uint32_t b0, uint32_t b1) {
    asm volatile("mma.sync.aligned.m16n8k16.row.col.f32.f16.f16.f32 "
                 "{%0,%1,%2,%3}, {%4,%5,%6,%7}, {%8,%9}, {%0,%1,%2,%3};"
                 : "+f"(c[0]), "+f"(c[1]), "+f"(c[2]), "+f"(c[3])
                 : "r"(a[0]), "r"(a[1]), "r"(a[2]), "r"(a[3]), "r"(b0), "r"(b1));
}
__device__ __forceinline__ void cp_async16(uint32_t dst, const void* src) {
    asm volatile("cp.async.cg.shared.global [%0], [%1], 16;\n" :: "r"(dst), "l"(src));
}
__device__ __forceinline__ void cp_commit() { asm volatile("cp.async.commit_group;\n"); }
template <int N> __device__ __forceinline__ void cp_wait() {
    asm volatile("cp.async.wait_group %0;\n" :: "n"(N));
}
__device__ __forceinline__ uint32_t packh2(float x, float y) {
    const __half2 h = __floats2half2_rn(x, y);
    return *(const uint32_t*)&h;
}

// ---------------------------------------------------------------------------
// fused float -> half conversion (hs + 4 weights)
// ---------------------------------------------------------------------------
__global__ void f2h_all(const float* __restrict__ hs,
                        const float* __restrict__ w0, const float* __restrict__ w1,
                        const float* __restrict__ w2, const float* __restrict__ w3,
                        __half* __restrict__ hh, __half* __restrict__ wh)
{
    const int nAct4 = TT * EE / 4;
    const int nW4   = EE * EE / 4;
    int i = blockIdx.x * blockDim.x + threadIdx.x;

    const float* src; __half* dst; int j;
    if (i < nAct4) { src = hs; dst = hh; j = i; }
    else {
        int t = i - nAct4;
        int w = t / nW4;
        j = t - w * nW4;
        src = (w == 0) ? w0 : (w == 1) ? w1 : (w == 2) ? w2 : w3;
        dst = wh + (size_t)w * EE * EE;
    }
    float4 v = ((const float4*)src)[j];
    __half2* o = (__half2*)dst;
    o[2 * j]     = __floats2half2_rn(v.x, v.y);
    o[2 * j + 1] = __floats2half2_rn(v.z, v.w);
}

// ---------------------------------------------------------------------------
// mask compaction: block-diagonal of (T,T) fp32 -> (T, L) half
// ---------------------------------------------------------------------------
__global__ void mask_compact(const float* __restrict__ mask, __half* __restrict__ mh)
{
    const int i = blockIdx.x * blockDim.x + threadIdx.x;
    const int r  = i >> 8;
    const int c4 = (i & 255) * 4;
    const int seg = r >> 10;
    float4 v = *(const float4*)&mask[(size_t)r * TT + (size_t)seg * LL + c4];
    __half2* o = (__half2*)&mh[(size_t)r * LL + c4];
    o[0] = __floats2half2_rn(v.x, v.y);
    o[1] = __floats2half2_rn(v.z, v.w);
}

// ---------------------------------------------------------------------------
// FP16 mma.sync GEMM v3 (round-13 best): block tile 128x64, BK=32, 3-stage,
// 8 warps (4x2), warp tile 32x32, 4 CTAs/SM.
// ---------------------------------------------------------------------------
#define GH      40
#define ABY2    (128 * GH * 2)
#define BBY2    (64 * GH * 2)
#define STGB2   (ABY2 + BBY2)
#define NST2    3
#define NSLAB   (EE / 32)

__device__ __forceinline__ void frag_offsets2(int warp, int lane, uint32_t* aoff, uint32_t* boff)
{
    const int mW = (warp >> 1) * 32;
    const int nW = (warp & 1) * 32;
#pragma unroll
    for (int mi = 0; mi < 2; mi++)
        aoff[mi] = (uint32_t)(((mW + mi * 16 + (lane & 15)) * GH + ((lane >> 4) << 3)) << 1);
#pragma unroll
    for (int np = 0; np < 2; np++)
        boff[np] = (uint32_t)(((nW + np * 16 + (lane & 7) + ((lane >> 4) << 3)) * GH
                               + (((lane >> 3) & 1) << 3)) << 1) + ABY2;
}

__device__ __forceinline__ void gemm_core2(
    const __half* __restrict__ A, const __half* __restrict__ B, float c[2][4][4],
    uint32_t smemBase, int tid, int rowBase, int colBase,
    const uint32_t* aoff, const uint32_t* boff)
{
    const int lr = tid >> 2;
    const int lc = (tid & 3) * 8;
    const __half* Aptr = A + (size_t)(rowBase + lr) * EE + lc;
    const __half* Bptr = B + (size_t)(colBase + lr) * EE + lc;
    const uint32_t sA0 = smemBase + (uint32_t)((lr * GH + lc) * 2);
    const uint32_t sA1 = smemBase + (uint32_t)(((lr + 64) * GH + lc) * 2);
    const uint32_t sB0 = smemBase + ABY2 + (uint32_t)((lr * GH + lc) * 2);

#pragma unroll
    for (int st = 0; st < NST2 - 1; st++) {
        const uint32_t bb = st * STGB2;
        const int k0 = st * 32;
        cp_async16(sA0 + bb, Aptr + k0);
        cp_async16(sA1 + bb, Aptr + (size_t)64 * EE + k0);
        cp_async16(sB0 + bb, Bptr + k0);
        cp_commit();
    }

    for (int s = 0; s < NSLAB; s++) {
        cp_wait<NST2 - 2>();
        __syncthreads();

        const int sn = s + NST2 - 1;
        if (sn < NSLAB) {
            const uint32_t nb = (uint32_t)(sn % NST2) * STGB2;
            const int k0 = sn * 32;
            cp_async16(sA0 + nb, Aptr + k0);
            cp_async16(sA1 + nb, Aptr + (size_t)64 * EE + k0);
            cp_async16(sB0 + nb, Bptr + k0);
        }
        cp_commit();

        const uint32_t bb = (uint32_t)(s % NST2) * STGB2;
#pragma unroll
        for (int kk = 0; kk < 2; kk++) {
            const uint32_t ko = (uint32_t)(kk * 32);
            uint32_t a[2][4], b[2][4];
#pragma unroll
            for (int mi = 0; mi < 2; mi++)
                ldsm4(a[mi], smemBase + bb + aoff[mi] + ko);
#pragma unroll
            for (int np = 0; np < 2; np++)
                ldsm4(b[np], smemBase + bb + boff[np] + ko);
#pragma unroll
            for (int mi = 0; mi < 2; mi++)
#pragma unroll
                for (int nj = 0; nj < 4; nj++) {
                    const int np = nj >> 1, hb = (nj & 1) << 1;
                    mma16(c[mi][nj], a[mi], b[np][hb], b[np][hb + 1]);
                }
        }
    }
}

// QKV fused projection GEMM: grid (16, 64, 3)
__global__ __launch_bounds__(256, 4)
void gemm_qkv(const __half* __restrict__ A, const __half* __restrict__ W,
              const float* __restrict__ bq, const float* __restrict__ bv,
              __half* __restrict__ Q, __half* __restrict__ K, __half* __restrict__ Vt)
{
    extern __shared__ char smc[];
    const uint32_t smemBase = (uint32_t)__cvta_generic_to_shared(smc);

    const int tid  = threadIdx.x;
    const int warp = tid >> 5;
    const int lane = tid & 31;
    const int z    = blockIdx.z;
    const int rowBase = blockIdx.y * 128;
    const int colBase = blockIdx.x * 64;

    uint32_t aoff[2], boff[2];
    frag_offsets2(warp, lane, aoff, boff);

    float c[2][4][4];
#pragma unroll
    for (int mi = 0; mi < 2; mi++)
#pragma unroll
        for (int nj = 0; nj < 4; nj++)
#pragma unroll
            for (int r = 0; r < 4; r++) c[mi][nj][r] = 0.f;

    gemm_core2(A, W + (size_t)z * EE * EE, c, smemBase, tid, rowBase, colBase, aoff, boff);

    const float* bias = (z == 0) ? bq : (z == 2) ? bv : nullptr;
    const int mW = (warp >> 1) * 32;
    const int nW = (warp & 1) * 32;

    if (z != 2) {
        __half* Cp = (z == 0) ? Q : K;
#pragma unroll
        for (int nj = 0; nj < 4; nj++) {
            const int col = colBase + nW + nj * 8 + (lane & 3) * 2;
            const float b0 = bias ? bias[col]     : 0.f;
            const float b1 = bias ? bias[col + 1] : 0.f;
#pragma unroll
            for (int mi = 0; mi < 2; mi++) {
                const int row = rowBase + mW + mi * 16 + (lane >> 2);
                *(__half2*)&Cp[(size_t)row * EE + col] =
                    __floats2half2_rn(c[mi][nj][0] + b0, c[mi][nj][1] + b1);
                *(__half2*)&Cp[(size_t)(row + 8) * EE + col] =
                    __floats2half2_rn(c[mi][nj][2] + b0, c[mi][nj][3] + b1);
            }
        }
    } else {
        __syncthreads();
        __half* st = (__half*)smc;       // [64 cols][136]
#pragma unroll
        for (int nj = 0; nj < 4; nj++) {
            const int cl = nW + nj * 8 + (lane & 3) * 2;
            const float b0 = bias[colBase + cl];
            const float b1 = bias[colBase + cl + 1];
#pragma unroll
            for (int mi = 0; mi < 2; mi++) {
                const int rl = mW + mi * 16 + (lane >> 2);
                st[cl * 136 + rl]           = __float2half_rn(c[mi][nj][0] + b0);
                st[(cl + 1) * 136 + rl]     = __float2half_rn(c[mi][nj][1] + b1);
                st[cl * 136 + rl + 8]       = __float2half_rn(c[mi][nj][2] + b0);
                st[(cl + 1) * 136 + rl + 8] = __float2half_rn(c[mi][nj][3] + b1);
            }
        }
        __syncthreads();
        const int col = tid >> 2;
        const int ro  = (tid & 3) * 32;
        const __half* src = &st[col * 136 + ro];
        __half* dst = &Vt[(size_t)(colBase + col) * TT + rowBase + ro];
#pragma unroll
        for (int p = 0; p < 4; p++)
            *(uint4*)(dst + 8 * p) = *(const uint4*)(src + 8 * p);
    }
}

// Output projection GEMM: C float + bias. grid (16, 64)
__global__ __launch_bounds__(256, 4)
void gemm_out(const __half* __restrict__ A, const __half* __restrict__ B,
              const float* __restrict__ bias, float* __restrict__ C)
{
    extern __shared__ char smc[];
    const uint32_t smemBase = (uint32_t)__cvta_generic_to_shared(smc);

    const int tid  = threadIdx.x;
    const int warp = tid >> 5;
    const int lane = tid & 31;
    const int rowBase = blockIdx.y * 128;
    const int colBase = blockIdx.x * 64;

    uint32_t aoff[2], boff[2];
    frag_offsets2(warp, lane, aoff, boff);

    float c[2][4][4];
#pragma unroll
    for (int mi = 0; mi < 2; mi++)
#pragma unroll
        for (int nj = 0; nj < 4; nj++)
#pragma unroll
            for (int r = 0; r < 4; r++) c[mi][nj][r] = 0.f;

    gemm_core2(A, B, c, smemBase, tid, rowBase, colBase, aoff, boff);

    const int mW = (warp >> 1) * 32;
    const int nW = (warp & 1) * 32;
#pragma unroll
    for (int nj = 0; nj < 4; nj++) {
        const int col = colBase + nW + nj * 8 + (lane & 3) * 2;
        const float b0 = bias[col], b1 = bias[col + 1];
#pragma unroll
        for (int mi = 0; mi < 2; mi++) {
            const int row = rowBase + mW + mi * 16 + (lane >> 2);
            *(float2*)&C[(size_t)row * EE + col] =
                make_float2(c[mi][nj][0] + b0, c[mi][nj][1] + b1);
            *(float2*)&C[(size_t)(row + 8) * EE + col] =
                make_float2(c[mi][nj][2] + b0, c[mi][nj][3] + b1);
        }
    }
}

// ---------------------------------------------------------------------------
// FP16 tensor-core flash attention v5 — split-key warps:
// CTA = 64 q-rows; 8 warps = (4 row-groups) x (2 key-halves).
// Warp (wr, kw): S and partial O for rows wr*16.. over keys kw*32..kw*32+31.
// Each warp ldsm's only HALF the K/V tiles. Single-pass softmax (additive over
// key halves). Epilogue: kw=1 partial O + row sums -> smem, kw=0 adds,
// normalizes, writes. P stays in registers; Q frags in registers.
// grid (HH, LL/64, NSEG) = (16,16,8), 256 threads.
// ---------------------------------------------------------------------------
#define AS      72
#define KVBYTES (64 * AS * 2)            // 9216
#define KOFFB(b) ((b) * 2 * KVBYTES)
#define VOFFB(b) (KOFFB(b) + KVBYTES)
#define ASMEM   (4 * KVBYTES)            // 36864 (also covers reduce buffers)
#define ORSTR   66                       // O-reduce row stride (floats)

__global__ __launch_bounds__(256, 2)
void attn_h(const __half* __restrict__ maskh)
{
    extern __shared__ char smc[];
    const uint32_t smemBase = (uint32_t)__cvta_generic_to_shared(smc);

    const int h   = blockIdx.x;
    const int q0  = blockIdx.y * 64;
    const int seg = blockIdx.z;
    const int tid = threadIdx.x;
    const int warp = tid >> 5;
    const int lane = tid & 31;
    const int wr  = warp & 3;            // row group
    const int kw  = warp >> 2;           // key half
    const int r0 = lane >> 2;
    const int cb = (lane & 3) * 2;

    // ---- stage Q tile (64 rows) into smem, ldsm into regs ----
    {
        __half* Qstage = (__half*)smc;
        for (int i = tid; i < 64 * 8; i += 256) {
            const int r = i >> 3, c8 = (i & 7) * 8;
            *(uint4*)&Qstage[r * AS + c8] =
                *(const uint4*)&g_qh[(size_t)(seg * LL + q0 + r) * EE + h * DD + c8];
        }
    }
    __syncthreads();

    uint32_t qf[4][4];
    {
        const uint32_t qoff = smemBase
            + (uint32_t)(((wr * 16 + (lane & 15)) * AS + ((lane >> 4) << 3)) << 1);
#pragma unroll
        for (int kd = 0; kd < 4; kd++)
            ldsm4(qf[kd], qoff + (uint32_t)(kd * 32));
    }
    __syncthreads();   // staging area free for K/V pipeline

    // K frag offsets: keys kw*32 + np*16 (np=0,1). V frag offsets: d rows np*16 (np=0..3).
    uint32_t koff[2], voff[4];
#pragma unroll
    for (int np = 0; np < 2; np++)
        koff[np] = (uint32_t)(((kw * 32 + np * 16 + (lane & 7) + ((lane >> 4) << 3)) * AS
                               + (((lane >> 3) & 1) << 3)) << 1);
#pragma unroll
    for (int np = 0; np < 4; np++)
        voff[np] = (uint32_t)(((np * 16 + (lane & 7) + ((lane >> 4) << 3)) * AS
                               + (((lane >> 3) & 1) << 3)) << 1);
    const uint32_t vko = (uint32_t)(kw * 64);     // key byte offset into Vt rows

    const int ch0 = tid * 2;
    const __half* kbase = &g_kh[(size_t)(seg * LL) * EE + h * DD];
    const __half* vbase = &g_vth[(size_t)(h * DD) * TT + seg * LL];
    const uint32_t* mrow0 = (const uint32_t*)&maskh[(size_t)(seg * LL + q0 + wr * 16 + r0) * LL];
    const uint32_t* mrow1 = mrow0 + 8 * (LL / 2);

    float o[8][4];
#pragma unroll
    for (int nj = 0; nj < 8; nj++)
#pragma unroll
        for (int r = 0; r < 4; r++) o[nj][r] = 0.f;
    float lrow[2] = {0.f, 0.f};

    // prologue: tile 0 -> buffer 0
    {
#pragma unroll
        for (int u = 0; u < 2; u++) {
            const int ch = ch0 + u;
            const int r = ch >> 3, c8 = (ch & 7) * 8;
            cp_async16(smemBase + KOFFB(0) + (uint32_t)((r * AS + c8) << 1),
                       kbase + (size_t)r * EE + c8);
            cp_async16(smemBase + VOFFB(0) + (uint32_t)((r * AS + c8) << 1),
                       vbase + (size_t)r * TT + c8);
        }
        cp_commit();
    }

    for (int kt = 0; kt < 16; kt++) {
        const int k0 = kt * 64;
        cp_wait<0>();
        __syncthreads();

        if (kt + 1 < 16) {
            const int kn = (kt + 1) * 64;
            const uint32_t kb = smemBase + KOFFB((kt + 1) & 1);
            const uint32_t vb = smemBase + VOFFB((kt + 1) & 1);
#pragma unroll
            for (int u = 0; u < 2; u++) {
                const int ch = ch0 + u;
                const int r = ch >> 3, c8 = (ch & 7) * 8;
                cp_async16(kb + (uint32_t)((r * AS + c8) << 1),
                           kbase + (size_t)(kn + r) * EE + c8);
                cp_async16(vb + (uint32_t)((r * AS + c8) << 1),
                           vbase + (size_t)r * TT + kn + c8);
            }
        }
        cp_commit();

        const uint32_t kbuf = smemBase + KOFFB(kt & 1);
        const uint32_t vbuf = smemBase + VOFFB(kt & 1);

        // ---- mask prefetch (half2), this warp's 32-key half ----
        uint32_t mm0[4], mm1[4];
        {
            const int mc = (k0 + kw * 32 + cb) >> 1;
#pragma unroll
            for (int nj = 0; nj < 4; nj++) {
                mm0[nj] = mrow0[mc + nj * 4];
                mm1[nj] = mrow1[mc + nj * 4];
            }
        }

        // ---- S = Q @ K^T over this warp's 32 keys ----
        float s[4][4];
#pragma unroll
        for (int nj = 0; nj < 4; nj++)
#pragma unroll
            for (int r = 0; r < 4; r++) s[nj][r] = 0.f;

#pragma unroll
        for (int kd = 0; kd < 4; kd++) {
            const uint32_t ko = (uint32_t)(kd * 32);
            uint32_t b[2][4];
#pragma unroll
            for (int np = 0; np < 2; np++) ldsm4(b[np], kbuf + koff[np] + ko);
#pragma unroll
            for (int nj = 0; nj < 4; nj++) {
                const int np = nj >> 1, hb = (nj & 1) << 1;
                mma16(s[nj], qf[kd], b[np][hb], b[np][hb + 1]);
            }
        }

        // ---- scale + mask + exp, pack P into A-fragments ----
        uint32_t pa[2][4];
#pragma unroll
        for (int nj = 0; nj < 4; nj++) {
            const float2 m0 = __half22float2(*(const __half2*)&mm0[nj]);
            const float2 m1 = __half22float2(*(const __half2*)&mm1[nj]);
            s[nj][0] = __expf(s[nj][0] * 0.125f + m0.x);
            s[nj][1] = __expf(s[nj][1] * 0.125f + m0.y);
            s[nj][2] = __expf(s[nj][2] * 0.125f + m1.x);
            s[nj][3] = __expf(s[nj][3] * 0.125f + m1.y);
            lrow[0] += s[nj][0] + s[nj][1];
            lrow[1] += s[nj][2] + s[nj][3];
        }
#pragma unroll
        for (int kc = 0; kc < 2; kc++) {
            pa[kc][0] = packh2(s[2 * kc][0],     s[2 * kc][1]);
            pa[kc][1] = packh2(s[2 * kc][2],     s[2 * kc][3]);
            pa[kc][2] = packh2(s[2 * kc + 1][0], s[2 * kc + 1][1]);
            pa[kc][3] = packh2(s[2 * kc + 1][2], s[2 * kc + 1][3]);
        }

        // ---- O += P @ V over this warp's 32 keys ----
#pragma unroll
        for (int kc = 0; kc < 2; kc++) {
            const uint32_t ko = vko + (uint32_t)(kc * 32);
            uint32_t b[4][4];
#pragma unroll
            for (int np = 0; np < 4; np++) ldsm4(b[np], vbuf + voff[np] + ko);
#pragma unroll
            for (int nj = 0; nj < 8; nj++) {
                const int np = nj >> 1, hb = (nj & 1) << 1;
                mma16(o[nj], pa[kc], b[np][hb], b[np][hb + 1]);
            }
        }
    }

    // ---- per-warp row-sum reduce (4-lane groups) ----
    lrow[0] += __shfl_xor_sync(0xffffffffu, lrow[0], 1);
    lrow[0] += __shfl_xor_sync(0xffffffffu, lrow[0], 2);
    lrow[1] += __shfl_xor_sync(0xffffffffu, lrow[1], 1);
    lrow[1] += __shfl_xor_sync(0xffffffffu, lrow[1], 2);

    // ---- cross-key-half reduction via smem ----
    __syncthreads();                     // K/V buffers dead; reuse as reduce space
    float* ored = (float*)smc;           // [64][ORSTR]
    float* lred = (float*)(smc + 64 * ORSTR * 4);   // [64]
    const int rA = wr * 16 + r0;
    const int rB = rA + 8;

    if (kw == 1) {
#pragma unroll
        for (int nj = 0; nj < 8; nj++) {
            const int col = nj * 8 + cb;
            ored[rA * ORSTR + col]     = o[nj][0];
            ored[rA * ORSTR + col + 1] = o[nj][1];
            ored[rB * ORSTR + col]     = o[nj][2];
            ored[rB * ORSTR + col + 1] = o[nj][3];
        }
        if ((lane & 3) == 0) { lred[rA] = lrow[0]; lred[rB] = lrow[1]; }
    }
    __syncthreads();
    if (kw == 0) {
        const float inv0 = 1.f / (lrow[0] + lred[rA]);
        const float inv1 = 1.f / (lrow[1] + lred[rB]);
        const size_t row0 = (size_t)(seg * LL + q0 + rA);
#pragma unroll
        for (int nj = 0; nj < 8; nj++) {
            const int col = nj * 8 + cb;
            const float v00 = (o[nj][0] + ored[rA * ORSTR + col])     * inv0;
            const float v01 = (o[nj][1] + ored[rA * ORSTR + col + 1]) * inv0;
            const float v10 = (o[nj][2] + ored[rB * ORSTR + col])     * inv1;
            const float v11 = (o[nj][3] + ored[rB * ORSTR + col + 1]) * inv1;
            const int gc = h * DD + col;
            *(__half2*)&g_oh[row0 * EE + gc]       = __floats2half2_rn(v00, v01);
            *(__half2*)&g_oh[(row0 + 8) * EE + gc] = __floats2half2_rn(v10, v11);
        }
    }
}

// ---------------------------------------------------------------------------

extern "C" void kernel_launch(void* const* d_in, const int* in_sizes, int n_in,
                              void* d_out, int out_size)
{
    const float* hs   = (const float*)d_in[0];
    const float* mask = (const float*)d_in[2];
    const float* wq   = (const float*)d_in[3];
    const float* bq   = (const float*)d_in[4];
    const float* wk   = (const float*)d_in[5];
    const float* wv   = (const float*)d_in[6];
    const float* bv   = (const float*)d_in[7];
    const float* wo   = (const float*)d_in[8];
    const float* bo   = (const float*)d_in[9];
    float* out = (float*)d_out;

    __half *hh, *wh, *qh, *kh, *vth, *oh, *mkh;
    cudaGetSymbolAddress((void**)&hh,  g_hh);
    cudaGetSymbolAddress((void**)&wh,  g_wh);
    cudaGetSymbolAddress((void**)&qh,  g_qh);
    cudaGetSymbolAddress((void**)&kh,  g_kh);
    cudaGetSymbolAddress((void**)&vth, g_vth);
    cudaGetSymbolAddress((void**)&oh,  g_oh);
    cudaGetSymbolAddress((void**)&mkh, g_mkh);

    const int gsmem = NST2 * STGB2;               // 46080
    cudaFuncSetAttribute(gemm_qkv, cudaFuncAttributeMaxDynamicSharedMemorySize, gsmem);
    cudaFuncSetAttribute(gemm_out, cudaFuncAttributeMaxDynamicSharedMemorySize, gsmem);
    cudaFuncSetAttribute(attn_h, cudaFuncAttributeMaxDynamicSharedMemorySize, ASMEM);

    const int nConv = (TT * EE + 4 * EE * EE) / 4;
    f2h_all<<<nConv / 256, 256>>>(hs, wq, wk, wv, wo, hh, wh);
    mask_compact<<<TT * LL / 4 / 256, 256>>>(mask, mkh);

    gemm_qkv<<<dim3(EE / 64, TT / 128, 3), 256, gsmem>>>(hh, wh, bq, bv, qh, kh, vth);

    attn_h<<<dim3(HH, LL / 64, NSEG), 256, ASMEM>>>(mkh);

    gemm_out<<<dim3(EE / 64, TT / 128), 256, gsmem>>>(oh, wh + 3 * (size_t)EE * EE, bo, out);
}

// round 17
// speedup vs baseline: 1.0556x; 1.0556x over previous
#include <cuda_runtime.h>
#include <cuda_fp16.h>
#include <math.h>
#include <stdint.h>

#define TT   8192
#define EE   1024
#define HH   16
#define DD   64
#define NSEG 8
#define LL   1024

// Scratch (device globals — no allocation allowed in kernel_launch)
__device__ __half g_hh [TT * EE];       // hs in half
__device__ __half g_wh [4 * EE * EE];   // 4 weights in half
__device__ __half g_qh [TT * EE];       // Q projection (half)
__device__ __half g_kh [TT * EE];       // K projection (half)
__device__ __half g_vth[EE * TT];       // V projection, transposed [e][token]
__device__ __half g_oh [TT * EE];       // attention output (half)
__device__ __half g_mkh[TT * LL];       // compacted block-diagonal mask (half)

// ---------------------------------------------------------------------------
// helpers
// ---------------------------------------------------------------------------
__device__ __forceinline__ void ldsm4(uint32_t* r, uint32_t addr) {
    asm volatile("ldmatrix.sync.aligned.m8n8.x4.shared.b16 {%0,%1,%2,%3}, [%4];"
                 : "=r"(r[0]), "=r"(r[1]), "=r"(r[2]), "=r"(r[3]) : "r"(addr));
}
__device__ __forceinline__ void mma16(float* c, const uint32_t* a, uint32_t b0, uint32_t b1) {
    asm volatile("mma.sync.aligned.m16n8k16.row.col.f32.f16.f16.f32 "
                 "{%0,%1,%2,%3}, {%4,%5,%6,%7}, {%8,%9}, {%0,%1,%2,%3};"
                 : "+f"(c[0]), "+f"(c[1]), "+f"(c[2]), "+f"(c[3])
                 : "r"(a[0]), "r"(a[1]), "r"(a[2]), "r"(a[3]), "r"(b0), "r"(b1));
}
__device__ __forceinline__ void cp_async16(uint32_t dst, const void* src) {
    asm volatile("cp.async.cg.shared.global [%0], [%1], 16;\n" :: "r"(dst), "l"(src));
}
__device__ __forceinline__ void cp_commit() { asm volatile("cp.async.commit_group;\n"); }
template <int N> __device__ __forceinline__ void cp_wait() {
    asm volatile("cp.async.wait_group %0;\n" :: "n"(N));
}
__device__ __forceinline__ uint32_t packh2(float x, float y) {
    const __half2 h = __floats2half2_rn(x, y);
    return *(const uint32_t*)&h;
}

// ---------------------------------------------------------------------------
// fused conversions: hs->half, 4 weights->half, mask block-diagonal->half
// index space: [0, nAct4) hs | [nAct4, nAct4+4*nW4) weights | rest mask
// ---------------------------------------------------------------------------
__global__ void conv_all(const float* __restrict__ hs,
                         const float* __restrict__ w0, const float* __restrict__ w1,
                         const float* __restrict__ w2, const float* __restrict__ w3,
                         const float* __restrict__ mask,
                         __half* __restrict__ hh, __half* __restrict__ wh,
                         __half* __restrict__ mh)
{
    const int nAct4 = TT * EE / 4;
    const int nW4   = EE * EE / 4;
    const int nWAll = nAct4 + 4 * nW4;
    int i = blockIdx.x * blockDim.x + threadIdx.x;

    if (i < nWAll) {
        const float* src; __half* dst; int j;
        if (i < nAct4) { src = hs; dst = hh; j = i; }
        else {
            int t = i - nAct4;
            int w = t / nW4;
            j = t - w * nW4;
            src = (w == 0) ? w0 : (w == 1) ? w1 : (w == 2) ? w2 : w3;
            dst = wh + (size_t)w * EE * EE;
        }
        float4 v = ((const float4*)src)[j];
        __half2* o = (__half2*)dst;
        o[2 * j]     = __floats2half2_rn(v.x, v.y);
        o[2 * j + 1] = __floats2half2_rn(v.z, v.w);
    } else {
        const int t = i - nWAll;             // over TT*LL/4
        const int r  = t >> 8;               // 256 chunks per row
        const int c4 = (t & 255) * 4;
        const int seg = r >> 10;
        float4 v = *(const float4*)&mask[(size_t)r * TT + (size_t)seg * LL + c4];
        __half2* o = (__half2*)&mh[(size_t)r * LL + c4];
        o[0] = __floats2half2_rn(v.x, v.y);
        o[1] = __floats2half2_rn(v.z, v.w);
    }
}

// ---------------------------------------------------------------------------
// FP16 mma.sync GEMM (round-13 best): block tile 128x64, BK=32, 3-stage,
// 8 warps (4x2), warp tile 32x32, 4 CTAs/SM.
// ---------------------------------------------------------------------------
#define GH      40
#define ABY2    (128 * GH * 2)
#define BBY2    (64 * GH * 2)
#define STGB2   (ABY2 + BBY2)
#define NST2    3
#define NSLAB   (EE / 32)

__device__ __forceinline__ void frag_offsets2(int warp, int lane, uint32_t* aoff, uint32_t* boff)
{
    const int mW = (warp >> 1) * 32;
    const int nW = (warp & 1) * 32;
#pragma unroll
    for (int mi = 0; mi < 2; mi++)
        aoff[mi] = (uint32_t)(((mW + mi * 16 + (lane & 15)) * GH + ((lane >> 4) << 3)) << 1);
#pragma unroll
    for (int np = 0; np < 2; np++)
        boff[np] = (uint32_t)(((nW + np * 16 + (lane & 7) + ((lane >> 4) << 3)) * GH
                               + (((lane >> 3) & 1) << 3)) << 1) + ABY2;
}

__device__ __forceinline__ void gemm_core2(
    const __half* __restrict__ A, const __half* __restrict__ B, float c[2][4][4],
    uint32_t smemBase, int tid, int rowBase, int colBase,
    const uint32_t* aoff, const uint32_t* boff)
{
    const int lr = tid >> 2;
    const int lc = (tid & 3) * 8;
    const __half* Aptr = A + (size_t)(rowBase + lr) * EE + lc;
    const __half* Bptr = B + (size_t)(colBase + lr) * EE + lc;
    const uint32_t sA0 = smemBase + (uint32_t)((lr * GH + lc) * 2);
    const uint32_t sA1 = smemBase + (uint32_t)(((lr + 64) * GH + lc) * 2);
    const uint32_t sB0 = smemBase + ABY2 + (uint32_t)((lr * GH + lc) * 2);

#pragma unroll
    for (int st = 0; st < NST2 - 1; st++) {
        const uint32_t bb = st * STGB2;
        const int k0 = st * 32;
        cp_async16(sA0 + bb, Aptr + k0);
        cp_async16(sA1 + bb, Aptr + (size_t)64 * EE + k0);
        cp_async16(sB0 + bb, Bptr + k0);
        cp_commit();
    }

    for (int s = 0; s < NSLAB; s++) {
        cp_wait<NST2 - 2>();
        __syncthreads();

        const int sn = s + NST2 - 1;
        if (sn < NSLAB) {
            const uint32_t nb = (uint32_t)(sn % NST2) * STGB2;
            const int k0 = sn * 32;
            cp_async16(sA0 + nb, Aptr + k0);
            cp_async16(sA1 + nb, Aptr + (size_t)64 * EE + k0);
            cp_async16(sB0 + nb, Bptr + k0);
        }
        cp_commit();

        const uint32_t bb = (uint32_t)(s % NST2) * STGB2;
#pragma unroll
        for (int kk = 0; kk < 2; kk++) {
            const uint32_t ko = (uint32_t)(kk * 32);
            uint32_t a[2][4], b[2][4];
#pragma unroll
            for (int mi = 0; mi < 2; mi++)
                ldsm4(a[mi], smemBase + bb + aoff[mi] + ko);
#pragma unroll
            for (int np = 0; np < 2; np++)
                ldsm4(b[np], smemBase + bb + boff[np] + ko);
#pragma unroll
            for (int mi = 0; mi < 2; mi++)
#pragma unroll
                for (int nj = 0; nj < 4; nj++) {
                    const int np = nj >> 1, hb = (nj & 1) << 1;
                    mma16(c[mi][nj], a[mi], b[np][hb], b[np][hb + 1]);
                }
        }
    }
}

// QKV fused projection GEMM: grid (16, 64, 3)
__global__ __launch_bounds__(256, 4)
void gemm_qkv(const __half* __restrict__ A, const __half* __restrict__ W,
              const float* __restrict__ bq, const float* __restrict__ bv,
              __half* __restrict__ Q, __half* __restrict__ K, __half* __restrict__ Vt)
{
    extern __shared__ char smc[];
    const uint32_t smemBase = (uint32_t)__cvta_generic_to_shared(smc);

    const int tid  = threadIdx.x;
    const int warp = tid >> 5;
    const int lane = tid & 31;
    const int z    = blockIdx.z;
    const int rowBase = blockIdx.y * 128;
    const int colBase = blockIdx.x * 64;

    uint32_t aoff[2], boff[2];
    frag_offsets2(warp, lane, aoff, boff);

    float c[2][4][4];
#pragma unroll
    for (int mi = 0; mi < 2; mi++)
#pragma unroll
        for (int nj = 0; nj < 4; nj++)
#pragma unroll
            for (int r = 0; r < 4; r++) c[mi][nj][r] = 0.f;

    gemm_core2(A, W + (size_t)z * EE * EE, c, smemBase, tid, rowBase, colBase, aoff, boff);

    const float* bias = (z == 0) ? bq : (z == 2) ? bv : nullptr;
    const int mW = (warp >> 1) * 32;
    const int nW = (warp & 1) * 32;

    if (z != 2) {
        __half* Cp = (z == 0) ? Q : K;
#pragma unroll
        for (int nj = 0; nj < 4; nj++) {
            const int col = colBase + nW + nj * 8 + (lane & 3) * 2;
            const float b0 = bias ? bias[col]     : 0.f;
            const float b1 = bias ? bias[col + 1] : 0.f;
#pragma unroll
            for (int mi = 0; mi < 2; mi++) {
                const int row = rowBase + mW + mi * 16 + (lane >> 2);
                *(__half2*)&Cp[(size_t)row * EE + col] =
                    __floats2half2_rn(c[mi][nj][0] + b0, c[mi][nj][1] + b1);
                *(__half2*)&Cp[(size_t)(row + 8) * EE + col] =
                    __floats2half2_rn(c[mi][nj][2] + b0, c[mi][nj][3] + b1);
            }
        }
    } else {
        __syncthreads();
        __half* st = (__half*)smc;       // [64 cols][136]
#pragma unroll
        for (int nj = 0; nj < 4; nj++) {
            const int cl = nW + nj * 8 + (lane & 3) * 2;
            const float b0 = bias[colBase + cl];
            const float b1 = bias[colBase + cl + 1];
#pragma unroll
            for (int mi = 0; mi < 2; mi++) {
                const int rl = mW + mi * 16 + (lane >> 2);
                st[cl * 136 + rl]           = __float2half_rn(c[mi][nj][0] + b0);
                st[(cl + 1) * 136 + rl]     = __float2half_rn(c[mi][nj][1] + b1);
                st[cl * 136 + rl + 8]       = __float2half_rn(c[mi][nj][2] + b0);
                st[(cl + 1) * 136 + rl + 8] = __float2half_rn(c[mi][nj][3] + b1);
            }
        }
        __syncthreads();
        const int col = tid >> 2;
        const int ro  = (tid & 3) * 32;
        const __half* src = &st[col * 136 + ro];
        __half* dst = &Vt[(size_t)(colBase + col) * TT + rowBase + ro];
#pragma unroll
        for (int p = 0; p < 4; p++)
            *(uint4*)(dst + 8 * p) = *(const uint4*)(src + 8 * p);
    }
}

// Output projection GEMM: C float + bias. grid (16, 64)
__global__ __launch_bounds__(256, 4)
void gemm_out(const __half* __restrict__ A, const __half* __restrict__ B,
              const float* __restrict__ bias, float* __restrict__ C)
{
    extern __shared__ char smc[];
    const uint32_t smemBase = (uint32_t)__cvta_generic_to_shared(smc);

    const int tid  = threadIdx.x;
    const int warp = tid >> 5;
    const int lane = tid & 31;
    const int rowBase = blockIdx.y * 128;
    const int colBase = blockIdx.x * 64;

    uint32_t aoff[2], boff[2];
    frag_offsets2(warp, lane, aoff, boff);

    float c[2][4][4];
#pragma unroll
    for (int mi = 0; mi < 2; mi++)
#pragma unroll
        for (int nj = 0; nj < 4; nj++)
#pragma unroll
            for (int r = 0; r < 4; r++) c[mi][nj][r] = 0.f;

    gemm_core2(A, B, c, smemBase, tid, rowBase, colBase, aoff, boff);

    const int mW = (warp >> 1) * 32;
    const int nW = (warp & 1) * 32;
#pragma unroll
    for (int nj = 0; nj < 4; nj++) {
        const int col = colBase + nW + nj * 8 + (lane & 3) * 2;
        const float b0 = bias[col], b1 = bias[col + 1];
#pragma unroll
        for (int mi = 0; mi < 2; mi++) {
            const int row = rowBase + mW + mi * 16 + (lane >> 2);
            *(float2*)&C[(size_t)row * EE + col] =
                make_float2(c[mi][nj][0] + b0, c[mi][nj][1] + b1);
            *(float2*)&C[(size_t)(row + 8) * EE + col] =
                make_float2(c[mi][nj][2] + b0, c[mi][nj][3] + b1);
        }
    }
}

// ---------------------------------------------------------------------------
// FP16 tensor-core flash attention (round-15 best):
// - P stays in registers (S C-frag layout == PV A-frag layout)
// - Q fragments hoisted into registers (staged via K/V buffer area)
// - single-pass softmax; compacted half mask, prefetched
// smem: K/V double buffers only = 36864. grid (HH, LL/128, NSEG), 256 thr.
// ---------------------------------------------------------------------------
#define AS      72
#define KVBYTES (64 * AS * 2)
#define KOFFB(b) ((b) * 2 * KVBYTES)
#define VOFFB(b) (KOFFB(b) + KVBYTES)
#define ASMEM   (4 * KVBYTES)            // 36864

__global__ __launch_bounds__(256, 2)
void attn_h(const __half* __restrict__ maskh)
{
    extern __shared__ char smc[];
    const uint32_t smemBase = (uint32_t)__cvta_generic_to_shared(smc);

    const int h   = blockIdx.x;
    const int q0  = blockIdx.y * 128;
    const int seg = blockIdx.z;
    const int tid = threadIdx.x;
    const int warp = tid >> 5;
    const int lane = tid & 31;
    const int r0 = lane >> 2;
    const int cb = (lane & 3) * 2;

    // ---- stage Q tile into smem (K/V area, pre-pipeline), ldsm into regs ----
    {
        __half* Qstage = (__half*)smc;
        for (int i = tid; i < 128 * 8; i += 256) {
            const int r = i >> 3, c8 = (i & 7) * 8;
            *(uint4*)&Qstage[r * AS + c8] =
                *(const uint4*)&g_qh[(size_t)(seg * LL + q0 + r) * EE + h * DD + c8];
        }
    }
    __syncthreads();

    const uint32_t poff = smemBase
        + (uint32_t)(((warp * 16 + (lane & 15)) * AS + ((lane >> 4) << 3)) << 1);
    uint32_t qf[4][4];
#pragma unroll
    for (int kd = 0; kd < 4; kd++)
        ldsm4(qf[kd], poff + (uint32_t)(kd * 32));
    __syncthreads();   // staging area free for K/V pipeline

    uint32_t kvoff[4];
#pragma unroll
    for (int np = 0; np < 4; np++)
        kvoff[np] = (uint32_t)(((np * 16 + (lane & 7) + ((lane >> 4) << 3)) * AS
                                + (((lane >> 3) & 1) << 3)) << 1);

    const int ch0 = tid * 2;
    const __half* kbase = &g_kh[(size_t)(seg * LL) * EE + h * DD];
    const __half* vbase = &g_vth[(size_t)(h * DD) * TT + seg * LL];
    const uint32_t* mrow0 = (const uint32_t*)&maskh[(size_t)(seg * LL + q0 + warp * 16 + r0) * LL];
    const uint32_t* mrow1 = mrow0 + 8 * (LL / 2);

    float o[8][4];
#pragma unroll
    for (int nj = 0; nj < 8; nj++)
#pragma unroll
        for (int r = 0; r < 4; r++) o[nj][r] = 0.f;
    float lrow[2] = {0.f, 0.f};

    // prologue: tile 0 -> buffer 0
    {
#pragma unroll
        for (int u = 0; u < 2; u++) {
            const int ch = ch0 + u;
            const int r = ch >> 3, c8 = (ch & 7) * 8;
            cp_async16(smemBase + KOFFB(0) + (uint32_t)((r * AS + c8) << 1),
                       kbase + (size_t)r * EE + c8);
            cp_async16(smemBase + VOFFB(0) + (uint32_t)((r * AS + c8) << 1),
                       vbase + (size_t)r * TT + c8);
        }
        cp_commit();
    }

    for (int kt = 0; kt < 16; kt++) {
        const int k0 = kt * 64;
        cp_wait<0>();
        __syncthreads();

        if (kt + 1 < 16) {
            const int kn = (kt + 1) * 64;
            const uint32_t kb = smemBase + KOFFB((kt + 1) & 1);
            const uint32_t vb = smemBase + VOFFB((kt + 1) & 1);
#pragma unroll
            for (int u = 0; u < 2; u++) {
                const int ch = ch0 + u;
                const int r = ch >> 3, c8 = (ch & 7) * 8;
                cp_async16(kb + (uint32_t)((r * AS + c8) << 1),
                           kbase + (size_t)(kn + r) * EE + c8);
                cp_async16(vb + (uint32_t)((r * AS + c8) << 1),
                           vbase + (size_t)r * TT + kn + c8);
            }
        }
        cp_commit();

        const uint32_t kbuf = smemBase + KOFFB(kt & 1);
        const uint32_t vbuf = smemBase + VOFFB(kt & 1);

        // ---- mask prefetch (half2) ----
        uint32_t mm0[8], mm1[8];
        {
            const int mc = (k0 + cb) >> 1;
#pragma unroll
            for (int nj = 0; nj < 8; nj++) {
                mm0[nj] = mrow0[mc + nj * 4];
                mm1[nj] = mrow1[mc + nj * 4];
            }
        }

        // ---- S = Q @ K^T (Q frags in registers) ----
        float s[8][4];
#pragma unroll
        for (int nj = 0; nj < 8; nj++)
#pragma unroll
            for (int r = 0; r < 4; r++) s[nj][r] = 0.f;

#pragma unroll
        for (int kd = 0; kd < 4; kd++) {
            const uint32_t ko = (uint32_t)(kd * 32);
            uint32_t b[4][4];
#pragma unroll
            for (int np = 0; np < 4; np++) ldsm4(b[np], kbuf + kvoff[np] + ko);
#pragma unroll
            for (int nj = 0; nj < 8; nj++) {
                const int np = nj >> 1, hb = (nj & 1) << 1;
                mma16(s[nj], qf[kd], b[np][hb], b[np][hb + 1]);
            }
        }

        // ---- scale + mask + exp, pack P directly into A-fragments ----
        uint32_t pa[4][4];
#pragma unroll
        for (int nj = 0; nj < 8; nj++) {
            const float2 m0 = __half22float2(*(const __half2*)&mm0[nj]);
            const float2 m1 = __half22float2(*(const __half2*)&mm1[nj]);
            s[nj][0] = __expf(s[nj][0] * 0.125f + m0.x);
            s[nj][1] = __expf(s[nj][1] * 0.125f + m0.y);
            s[nj][2] = __expf(s[nj][2] * 0.125f + m1.x);
            s[nj][3] = __expf(s[nj][3] * 0.125f + m1.y);
            lrow[0] += s[nj][0] + s[nj][1];
            lrow[1] += s[nj][2] + s[nj][3];
        }
#pragma unroll
        for (int kc = 0; kc < 4; kc++) {
            pa[kc][0] = packh2(s[2 * kc][0],     s[2 * kc][1]);
            pa[kc][1] = packh2(s[2 * kc][2],     s[2 * kc][3]);
            pa[kc][2] = packh2(s[2 * kc + 1][0], s[2 * kc + 1][1]);
            pa[kc][3] = packh2(s[2 * kc + 1][2], s[2 * kc + 1][3]);
        }

        // ---- O += P @ V (P from registers) ----
#pragma unroll
        for (int kc = 0; kc < 4; kc++) {
            const uint32_t ko = (uint32_t)(kc * 32);
            uint32_t b[4][4];
#pragma unroll
            for (int np = 0; np < 4; np++) ldsm4(b[np], vbuf + kvoff[np] + ko);
#pragma unroll
            for (int nj = 0; nj < 8; nj++) {
                const int np = nj >> 1, hb = (nj & 1) << 1;
                mma16(o[nj], pa[kc], b[np][hb], b[np][hb + 1]);
            }
        }
    }

    // ---- final row-sum reduction + normalize + write (half) ----
    {
        lrow[0] += __shfl_xor_sync(0xffffffffu, lrow[0], 1);
        lrow[0] += __shfl_xor_sync(0xffffffffu, lrow[0], 2);
        lrow[1] += __shfl_xor_sync(0xffffffffu, lrow[1], 1);
        lrow[1] += __shfl_xor_sync(0xffffffffu, lrow[1], 2);
        const float inv0 = 1.f / lrow[0];
        const float inv1 = 1.f / lrow[1];
        const size_t row0 = (size_t)(seg * LL + q0 + warp * 16 + r0);
#pragma unroll
        for (int nj = 0; nj < 8; nj++) {
            const int col = h * DD + nj * 8 + cb;
            *(__half2*)&g_oh[row0 * EE + col] =
                __floats2half2_rn(o[nj][0] * inv0, o[nj][1] * inv0);
            *(__half2*)&g_oh[(row0 + 8) * EE + col] =
                __floats2half2_rn(o[nj][2] * inv1, o[nj][3] * inv1);
        }
    }
}

// ---------------------------------------------------------------------------

extern "C" void kernel_launch(void* const* d_in, const int* in_sizes, int n_in,
                              void* d_out, int out_size)
{
    const float* hs   = (const float*)d_in[0];
    const float* mask = (const float*)d_in[2];
    const float* wq   = (const float*)d_in[3];
    const float* bq   = (const float*)d_in[4];
    const float* wk   = (const float*)d_in[5];
    const float* wv   = (const float*)d_in[6];
    const float* bv   = (const float*)d_in[7];
    const float* wo   = (const float*)d_in[8];
    const float* bo   = (const float*)d_in[9];
    float* out = (float*)d_out;

    __half *hh, *wh, *qh, *kh, *vth, *oh, *mkh;
    cudaGetSymbolAddress((void**)&hh,  g_hh);
    cudaGetSymbolAddress((void**)&wh,  g_wh);
    cudaGetSymbolAddress((void**)&qh,  g_qh);
    cudaGetSymbolAddress((void**)&kh,  g_kh);
    cudaGetSymbolAddress((void**)&vth, g_vth);
    cudaGetSymbolAddress((void**)&oh,  g_oh);
    cudaGetSymbolAddress((void**)&mkh, g_mkh);

    const int gsmem = NST2 * STGB2;               // 46080
    cudaFuncSetAttribute(gemm_qkv, cudaFuncAttributeMaxDynamicSharedMemorySize, gsmem);
    cudaFuncSetAttribute(gemm_out, cudaFuncAttributeMaxDynamicSharedMemorySize, gsmem);
    cudaFuncSetAttribute(attn_h, cudaFuncAttributeMaxDynamicSharedMemorySize, ASMEM);

    // single fused conversion launch: hs + weights + mask compaction
    const int nConv = (TT * EE + 4 * EE * EE) / 4 + TT * LL / 4;
    conv_all<<<(nConv + 255) / 256, 256>>>(hs, wq, wk, wv, wo, mask, hh, wh, mkh);

    gemm_qkv<<<dim3(EE / 64, TT / 128, 3), 256, gsmem>>>(hh, wh, bq, bv, qh, kh, vth);

    attn_h<<<dim3(HH, LL / 128, NSEG), 256, ASMEM>>>(mkh);

    gemm_out<<<dim3(EE / 64, TT / 128), 256, gsmem>>>(oh, wh + 3 * (size_t)EE * EE, bo, out);
}